// round 8
// baseline (speedup 1.0000x reference)
#include <cuda_runtime.h>
#include <cuda_bf16.h>
#include <cstdint>

#define NROWS 8192
#define DIMS  512
#define BM    128
#define BK    64
#define NBLK  64                          /* 8192/128 */
#define NTILES 2080                       /* upper-triangular 64*65/2 */
#define PAD_K 72                          /* bf16 elems/row: 144B -> LDSM conflict-free */
#define A_BYTES (BM * PAD_K * 2)          /* 18432 */
#define STAGE_BYTES (2 * A_BYTES)         /* A+B per stage: 36864 B */
#define NSTAGE 3
#define DSMEM (NSTAGE * STAGE_BYTES)      /* 110592 B */

// ---------------- device scratch (no allocation allowed) ----------------
__device__ __nv_bfloat16 g_A[NROWS * DIMS];   // normalized reps, bf16
__device__ float g_pos[NROWS];
__device__ float g_neg[NROWS];
__device__ int   g_lab[NROWS];
__device__ int   g_cntp[8][128];              // per-label-block class histograms
__device__ int   g_tick;                      // self-resetting completion ticket

// ---------------- helpers ----------------
__device__ __forceinline__ uint32_t smem_u32(const void* p) {
    uint32_t a;
    asm("{ .reg .u64 t; cvta.to.shared.u64 t, %1; cvt.u32.u64 %0, t; }" : "=r"(a) : "l"(p));
    return a;
}
__device__ __forceinline__ void cp16(uint32_t dst, const void* src) {
    asm volatile("cp.async.cg.shared.global [%0], [%1], 16;" :: "r"(dst), "l"(src));
}
#define CP_COMMIT() asm volatile("cp.async.commit_group;" ::: "memory")
#define CP_WAIT1()  asm volatile("cp.async.wait_group 1;" ::: "memory")
#define CP_WAIT0()  asm volatile("cp.async.wait_group 0;" ::: "memory")

__device__ __forceinline__ void ldsm4(uint32_t addr, uint32_t& r0, uint32_t& r1,
                                      uint32_t& r2, uint32_t& r3) {
    asm volatile("ldmatrix.sync.aligned.m8n8.x4.shared.b16 {%0,%1,%2,%3}, [%4];"
        : "=r"(r0), "=r"(r1), "=r"(r2), "=r"(r3) : "r"(addr));
}
__device__ __forceinline__ void mma16816(float* d, uint32_t a0, uint32_t a1,
                                         uint32_t a2, uint32_t a3,
                                         uint32_t b0, uint32_t b1) {
    asm volatile("mma.sync.aligned.m16n8k16.row.col.f32.bf16.bf16.f32 "
        "{%0,%1,%2,%3}, {%4,%5,%6,%7}, {%8,%9}, {%0,%1,%2,%3};"
        : "+f"(d[0]), "+f"(d[1]), "+f"(d[2]), "+f"(d[3])
        : "r"(a0), "r"(a1), "r"(a2), "r"(a3), "r"(b0), "r"(b1));
}

// 2^t via magic round + deg-4 poly; t in [-0.1, 14.6]; rel err ~6e-5. FMA pipe only.
__device__ __forceinline__ float fast_exp2(float t) {
    float fn = t + 12582912.0f;                 // 1.5*2^23 magic round-to-nearest
    float f  = t - (fn - 12582912.0f);          // f in [-0.5, 0.5]
    float p  = fmaf(0.009618129f, f, 0.05550411f);
    p = fmaf(p, f, 0.2402265f);
    p = fmaf(p, f, 0.6931472f);
    p = fmaf(p, f, 1.0f);
    return __int_as_float(__float_as_int(p) + (__float_as_int(fn) << 23));
}
__device__ __forceinline__ float red4(float v) {     // sum over lane&3 group
    v += __shfl_xor_sync(0xffffffffu, v, 1);
    v += __shfl_xor_sync(0xffffffffu, v, 2);
    return v;
}
__device__ __forceinline__ float red8(float v) {     // sum over lane>>2 group
    v += __shfl_xor_sync(0xffffffffu, v, 4);
    v += __shfl_xor_sync(0xffffffffu, v, 8);
    v += __shfl_xor_sync(0xffffffffu, v, 16);
    return v;
}

// ---------------- fused normalize + label decode ----------------
// blocks 0..8191: row L2-normalize fp32 -> bf16 (+ zero g_pos/g_neg)
// blocks 8192..8199: decode 1024 labels each (int64/int32 sniff) + smem histogram
__global__ void k_norm(const float* __restrict__ reps, const unsigned int* __restrict__ raw) {
    int row = blockIdx.x;
    int tid = threadIdx.x;
    if (row < NROWS) {
        if (tid == 0) { g_pos[row] = 0.0f; g_neg[row] = 0.0f; }
        const float4* rp = (const float4*)(reps + (size_t)row * DIMS);
        float4 v = rp[tid];
        float ss = v.x * v.x + v.y * v.y + v.z * v.z + v.w * v.w;
        #pragma unroll
        for (int o = 16; o; o >>= 1) ss += __shfl_xor_sync(0xffffffffu, ss, o);
        __shared__ float ws[4];
        if ((tid & 31) == 0) ws[tid >> 5] = ss;
        __syncthreads();
        float inv = rsqrtf(ws[0] + ws[1] + ws[2] + ws[3]);
        __nv_bfloat162 p0 = __floats2bfloat162_rn(v.x * inv, v.y * inv);
        __nv_bfloat162 p1 = __floats2bfloat162_rn(v.z * inv, v.w * inv);
        __nv_bfloat162* op = (__nv_bfloat162*)(g_A + (size_t)row * DIMS + tid * 4);
        op[0] = p0; op[1] = p1;
    } else {
        int b = row - NROWS;                 // 0..7
        __shared__ unsigned snz;
        __shared__ int hist[128];
        if (tid == 0) snz = 0u;
        hist[tid] = 0;
        __syncthreads();
        // consistent int64-vs-int32 sniff: high words of the SAME first-512 window
        unsigned nz = 0;
        #pragma unroll
        for (int j = 0; j < 4; ++j) nz |= raw[2 * (tid + j * 128) + 1];
        if (nz) atomicOr(&snz, nz);
        __syncthreads();
        int w64 = (snz == 0u) ? 1 : 0;
        int base = b * 1024;
        #pragma unroll
        for (int k = 0; k < 8; ++k) {
            int i = base + k * 128 + tid;
            int v = (w64 ? (int)raw[2 * i] : (int)raw[i]) & 127;
            g_lab[i] = v;
            atomicAdd(&hist[v], 1);
        }
        __syncthreads();
        g_cntp[b][tid] = hist[tid];
    }
}

// ---------------- fused mma.sync tile kernel + register epilogue + final fold ----------------
extern __shared__ char smem_raw[];

__global__ void __launch_bounds__(256, 2) k_gemm(float* __restrict__ out) {
    // linear block -> upper-triangular (bi, bj), bi <= bj
    int b = blockIdx.x, bi = 0, rem = b;
    while (rem >= NBLK - bi) { rem -= NBLK - bi; ++bi; }
    int bj = bi + rem;

    char* sb = smem_raw;
    uint32_t sb32 = smem_u32(sb);
    __shared__ int labr[BM], labc[BM];
    __shared__ int s_last;

    int tid = threadIdx.x, wid = tid >> 5, lane = tid & 31;
    if (tid < 128) labr[tid] = g_lab[bi * BM + tid];
    else           labc[tid - 128] = g_lab[bj * BM + (tid - 128)];

    const char* Abase = (const char*)(g_A + (size_t)bi * BM * DIMS);
    const char* Bbase = (const char*)(g_A + (size_t)bj * BM * DIMS);

    // copy slice: row r (0..127), byte segment cs (0 or 64) of each 128B chunk
    int r  = tid >> 1;
    int cs = (tid & 1) * 64;
    uint32_t dA0 = sb32 + r * 144 + cs;
    const char* gA0 = Abase + (size_t)r * 1024 + cs;
    const char* gB0 = Bbase + (size_t)r * 1024 + cs;

    #pragma unroll
    for (int c = 0; c < 2; ++c) {     // prefetch chunks 0,1 into stages 0,1
        uint32_t dA = dA0 + c * STAGE_BYTES;
        #pragma unroll
        for (int i = 0; i < 4; ++i) {
            cp16(dA + i * 16,           gA0 + c * 128 + i * 16);
            cp16(dA + A_BYTES + i * 16, gB0 + c * 128 + i * 16);
        }
        CP_COMMIT();
    }

    int wm = wid & 3;        // 4 warp rows (32 rows each)
    int wn = wid >> 2;       // 2 warp cols (64 cols each)

    float acc[2][8][4];
    #pragma unroll
    for (int mt = 0; mt < 2; ++mt)
        #pragma unroll
        for (int nt = 0; nt < 8; ++nt)
            acc[mt][nt][0] = acc[mt][nt][1] = acc[mt][nt][2] = acc[mt][nt][3] = 0.0f;

    // ldmatrix lane address components (within a stage)
    uint32_t aRow = (uint32_t)(wm * 32 + (lane & 15));          // + mt*16
    uint32_t aOff = aRow * 144 + (lane >> 4) * 16;              // + kk*32
    uint32_t bRow = (uint32_t)(wn * 64 + ((lane >> 4) & 1) * 8 + (lane & 7));  // + ntp*16
    uint32_t bOff = A_BYTES + bRow * 144 + ((lane >> 3) & 1) * 16;             // + kk*32

    int sc = 0;
    for (int c = 0; c < 8; ++c) {
        if (c < 7) CP_WAIT1(); else CP_WAIT0();
        __syncthreads();                          // prior chunk fully consumed
        if (c + 2 < 8) {
            int sp = sc + 2; if (sp >= NSTAGE) sp -= NSTAGE;
            uint32_t dA = dA0 + sp * STAGE_BYTES;
            const char* gA = gA0 + (c + 2) * 128;
            const char* gB = gB0 + (c + 2) * 128;
            #pragma unroll
            for (int i = 0; i < 4; ++i) {
                cp16(dA + i * 16,           gA + i * 16);
                cp16(dA + A_BYTES + i * 16, gB + i * 16);
            }
            CP_COMMIT();
        }
        uint32_t stg = sb32 + sc * STAGE_BYTES;
        #pragma unroll
        for (int kk = 0; kk < 4; ++kk) {          // 4 k16-steps per 64-chunk
            uint32_t a[2][4], bf[8][2];
            #pragma unroll
            for (int mt = 0; mt < 2; ++mt)
                ldsm4(stg + aOff + mt * 16 * 144 + kk * 32,
                      a[mt][0], a[mt][1], a[mt][2], a[mt][3]);
            #pragma unroll
            for (int ntp = 0; ntp < 4; ++ntp)
                ldsm4(stg + bOff + ntp * 16 * 144 + kk * 32,
                      bf[ntp * 2][0], bf[ntp * 2][1], bf[ntp * 2 + 1][0], bf[ntp * 2 + 1][1]);
            #pragma unroll
            for (int mt = 0; mt < 2; ++mt)
                #pragma unroll
                for (int nt = 0; nt < 8; ++nt)
                    mma16816(acc[mt][nt], a[mt][0], a[mt][1], a[mt][2], a[mt][3],
                             bf[nt][0], bf[nt][1]);
        }
        ++sc; if (sc >= NSTAGE) sc = 0;
    }

    // ---- register epilogue: streamed per column group (low reg pressure) ----
    bool isdiag = (bi == bj);
    int lr[4];
    #pragma unroll
    for (int mt = 0; mt < 2; ++mt)
        #pragma unroll
        for (int h = 0; h < 2; ++h)
            lr[mt * 2 + h] = labr[wm * 32 + mt * 16 + h * 8 + (lane >> 2)];

    float rpos[4] = {0, 0, 0, 0}, rneg[4] = {0, 0, 0, 0};
    int rbase = wm * 32 + (lane >> 2);
    int cqbase = wn * 64 + 2 * (lane & 3);

    #pragma unroll
    for (int nt = 0; nt < 8; ++nt) {
        int lc0 = labc[cqbase + nt * 8];
        int lc1 = labc[cqbase + nt * 8 + 1];
        float cp0 = 0.0f, cp1 = 0.0f, cn0 = 0.0f, cn1 = 0.0f;
        #pragma unroll
        for (int mt = 0; mt < 2; ++mt)
            #pragma unroll
            for (int e = 0; e < 4; ++e) {
                int h = e >> 1, q = e & 1;
                // t = s*log2e, s = (1+cos)/2/TEMP + EPS/TEMP, M = 0
                float t = fmaf(acc[mt][nt][e], 7.21347520f, 7.21347534f);
                int lcq = q ? lc1 : lc0;
                if (lr[mt * 2 + h] == lcq) {
                    float s = t * 0.69314718f;
                    int rrl = rbase + mt * 16 + h * 8;
                    int ccl = cqbase + nt * 8 + q;
                    if (!(isdiag && rrl == ccl)) rpos[mt * 2 + h] += s;
                    if (q) cp1 += s; else cp0 += s;
                } else {
                    float ex = fast_exp2(t);
                    rneg[mt * 2 + h] += ex;
                    if (q) cn1 += ex; else cn0 += ex;
                }
            }
        if (!isdiag) {   // column scatter via symmetry, immediately reduced
            float p0 = red8(cp0), n0 = red8(cn0);
            float p1 = red8(cp1), n1 = red8(cn1);
            if (lane < 4) {
                int cc = bj * BM + wn * 64 + nt * 8 + 2 * lane;
                atomicAdd(&g_pos[cc], p0);
                atomicAdd(&g_neg[cc], n0);
                atomicAdd(&g_pos[cc + 1], p1);
                atomicAdd(&g_neg[cc + 1], n1);
            }
        }
    }
    // row scatter
    #pragma unroll
    for (int i = 0; i < 4; ++i) {
        float p = red4(rpos[i]), n = red4(rneg[i]);
        if ((lane & 3) == 0) {
            int rr = bi * BM + rbase + (i >> 1) * 16 + (i & 1) * 8;
            atomicAdd(&g_pos[rr], p);
            atomicAdd(&g_neg[rr], n);
        }
    }

    // ---- completion ticket: last CTA folds the final reduction ----
    __threadfence();
    __syncthreads();
    if (tid == 0) s_last = (atomicAdd(&g_tick, 1) == NTILES - 1);
    __syncthreads();
    if (s_last) {
        __threadfence();
        float* fred = (float*)sb;            // stages are dead; reuse dynamic smem
        float* scnt = fred + 512;
        if (tid < 128) {
            int c = 0;
            #pragma unroll
            for (int p = 0; p < 8; ++p) c += g_cntp[p][tid];
            scnt[tid] = (float)(c - 1);
        }
        __syncthreads();
        float lsum = 0.0f, msum = 0.0f;
        for (int i = tid; i < NROWS; i += 256) {
            float cnt  = scnt[g_lab[i]];
            float posr = g_pos[i] / (cnt + 1e-8f);
            float loss = logf(g_neg[i] + 1e-8f) - posr;
            if (loss > 0.0f) { lsum += loss; msum += 1.0f; }
        }
        fred[tid] = lsum; fred[256 + tid] = msum;
        __syncthreads();
        #pragma unroll
        for (int o = 128; o; o >>= 1) {
            if (tid < o) { fred[tid] += fred[tid + o]; fred[256 + tid] += fred[256 + tid + o]; }
            __syncthreads();
        }
        if (tid == 0) {
            out[0] = fred[0] / (fred[256] + 1e-8f);
            atomicExch(&g_tick, 0);          // reset for next graph replay
        }
    }
}

extern "C" void kernel_launch(void* const* d_in, const int* in_sizes, int n_in,
                              void* d_out, int out_size) {
    const float* reps = (const float*)d_in[0];
    const unsigned int* labraw = (const unsigned int*)d_in[1];
    float* out = (float*)d_out;

    cudaFuncSetAttribute(k_gemm, cudaFuncAttributeMaxDynamicSharedMemorySize, DSMEM);

    k_norm<<<NROWS + 8, 128>>>(reps, labraw);
    k_gemm<<<NTILES, 256, DSMEM>>>(out);
}